// round 2
// baseline (speedup 1.0000x reference)
#include <cuda_runtime.h>
#include <cstddef>

// Problem constants
#define BB   2
#define TT   2048
#define CC   1024
#define DIM_ 1024
#define HH   16
#define HD_  64
#define M1   (BB*TT)        // 4096 rows of x / attn-out
#define N1   (3*DIM_)       // 3072 qkv cols
#define KDIM 1024           // reduction dim for both big GEMMs
#define NROWS (BB*HH*TT)    // 65536 (b,h,t) rows

// ---------------------------------------------------------------------------
// Scratch (device globals — no allocations allowed)
// ---------------------------------------------------------------------------
__device__ float g_q[(size_t)BB*HH*TT*HD_];     // 16 MB
__device__ float g_k[(size_t)BB*HH*TT*HD_];     // 16 MB
__device__ float g_v[(size_t)BB*HH*TT*HD_];     // 16 MB
__device__ float g_attn[(size_t)BB*TT*DIM_];    // 16 MB, (B,T,DIM) layout
__device__ float g_qn[NROWS];
__device__ float g_kn[NROWS];

// ---------------------------------------------------------------------------
// Fast 2^t for t <= ~0 (FMA-pipe only; avoids MUFU throughput wall).
// Degree-6 Taylor of 2^f on [0,1): max rel err ~8e-6.
// ---------------------------------------------------------------------------
__device__ __forceinline__ float fexp2(float t) {
    t = fmaxf(t, -125.0f);
    float fi = floorf(t);
    float f  = t - fi;                       // [0,1)
    float p  = 1.5403530e-4f;
    p = fmaf(p, f, 1.3333558e-3f);
    p = fmaf(p, f, 9.6181291e-3f);
    p = fmaf(p, f, 5.5504109e-2f);
    p = fmaf(p, f, 2.4022651e-1f);
    p = fmaf(p, f, 6.9314718e-1f);
    p = fmaf(p, f, 1.0f);
    float sc = __int_as_float(((int)fi + 127) << 23);
    return p * sc;
}

// ---------------------------------------------------------------------------
// SGEMM 128x128x16, 256 threads, 8x8 microtile.
// MODE 0: C = x @ Wqkv + bqkv, scattered into g_q/g_k/g_v in (B,H,T,HD) layout
// MODE 1: C = g_attn @ Wproj + bproj -> d_out (row-major 4096x1024)
// ---------------------------------------------------------------------------
template <int MODE>
__global__ void __launch_bounds__(256)
sgemm_kernel(const float* __restrict__ A_in,
             const float* __restrict__ Bm,
             const float* __restrict__ bias,
             float* __restrict__ Cout,
             int Ncols)
{
    __shared__ float As[16][128];   // transposed A tile: As[k][m]
    __shared__ float Bs[16][128];   // Bs[k][n]

    const float* A = (MODE == 0) ? A_in : g_attn;

    const int tid = threadIdx.x;
    const int m0  = blockIdx.y * 128;
    const int n0  = blockIdx.x * 128;
    const int ty  = tid >> 4;       // 0..15
    const int tx  = tid & 15;       // 0..15

    float acc[8][8];
#pragma unroll
    for (int i = 0; i < 8; i++)
#pragma unroll
        for (int j = 0; j < 8; j++) acc[i][j] = 0.f;

    for (int k0 = 0; k0 < KDIM; k0 += 16) {
        // A tile 128x16 (transpose into smem)
#pragma unroll
        for (int p = 0; p < 2; p++) {
            int id = tid + p * 256;          // 0..511 float4 ids
            int r  = id >> 2;                // row 0..127
            int c4 = id & 3;                 // 0..3
            float4 v = *(const float4*)(A + (size_t)(m0 + r) * KDIM + k0 + c4 * 4);
            As[c4*4+0][r] = v.x; As[c4*4+1][r] = v.y;
            As[c4*4+2][r] = v.z; As[c4*4+3][r] = v.w;
        }
        // B tile 16x128
#pragma unroll
        for (int p = 0; p < 2; p++) {
            int id = tid + p * 256;
            int r  = id >> 5;                // 0..15
            int c4 = id & 31;                // 0..31
            *(float4*)(&Bs[r][c4*4]) =
                *(const float4*)(Bm + (size_t)(k0 + r) * Ncols + n0 + c4 * 4);
        }
        __syncthreads();

#pragma unroll
        for (int kk = 0; kk < 16; kk++) {
            float a[8], b[8];
#pragma unroll
            for (int i = 0; i < 8; i++) a[i] = As[kk][ty*8 + i];
#pragma unroll
            for (int j = 0; j < 8; j++) b[j] = Bs[kk][tx*8 + j];
#pragma unroll
            for (int i = 0; i < 8; i++)
#pragma unroll
                for (int j = 0; j < 8; j++)
                    acc[i][j] = fmaf(a[i], b[j], acc[i][j]);
        }
        __syncthreads();
    }

    // Epilogue
#pragma unroll
    for (int i = 0; i < 8; i++) {
        int m  = m0 + ty*8 + i;
        int b_ = m >> 11;          // / 2048
        int t  = m & 2047;
#pragma unroll
        for (int j = 0; j < 8; j++) {
            int n = n0 + tx*8 + j;
            float val = acc[i][j] + bias[n];
            if (MODE == 0) {
                int s = n >> 10;          // 0:q 1:k 2:v
                int h = (n >> 6) & 15;
                int d = n & 63;
                size_t idx = ((size_t)(b_*HH + h) * TT + t) * HD_ + d;
                float* dst = (s == 0) ? g_q : (s == 1) ? g_k : g_v;
                dst[idx] = val;
            } else {
                Cout[(size_t)m * Ncols + n] = val;
            }
        }
    }
}

// ---------------------------------------------------------------------------
// Row norms: one warp per (b,h,t) row of 64 elems; both q and k.
// ---------------------------------------------------------------------------
__global__ void norms_kernel()
{
    int w    = (blockIdx.x * blockDim.x + threadIdx.x) >> 5;
    int lane = threadIdx.x & 31;
    if (w >= NROWS) return;
    float2 a = ((const float2*)(g_q + (size_t)w * HD_))[lane];
    float2 b = ((const float2*)(g_k + (size_t)w * HD_))[lane];
    float sq = a.x*a.x + a.y*a.y;
    float sk = b.x*b.x + b.y*b.y;
#pragma unroll
    for (int off = 16; off; off >>= 1) {
        sq += __shfl_xor_sync(0xFFFFFFFFu, sq, off);
        sk += __shfl_xor_sync(0xFFFFFFFFu, sk, off);
    }
    if (lane == 0) { g_qn[w] = sq; g_kn[w] = sk; }
}

// ---------------------------------------------------------------------------
// Attention: CTA = (bh, 64-row i-tile). Holds K-tile + O-accumulator;
// streams 64-wide Q/V j-tiles. S = K·Qᵀ, P = 2^(c1·dist2·log2e), O += P·V.
// Writes directly in (B,T,DIM) layout so proj GEMM reads contiguously.
// smem: Kt[64*64] + QV[64*64] + P[64*64] = 49152 B exactly (static, no
// cudaFuncSetAttribute needed). Q stored transposed with XOR bank swizzle.
// ---------------------------------------------------------------------------
__device__ __forceinline__ int qswz(int d, int j) {
    return d * 64 + (j ^ (d & 31));
}

__global__ void __launch_bounds__(256)
attn_kernel(const float* __restrict__ sigp)
{
    __shared__ float sm[3 * 64 * 64];
    float* Kt = sm;                    // [i][d]   stride 64
    float* QV = sm + 64*64;            // Q: swizzled [d][j] ; V: [j][d] stride 64
    float* P  = sm + 2*64*64;          // [i][j]   stride 64

    const int tid = threadIdx.x;
    const int bh  = blockIdx.y;                  // 0..31
    const int i0  = blockIdx.x * 64;
    const int ty  = tid >> 4;                    // 0..15 -> i block
    const int tx  = tid & 15;                    // 0..15 -> j/d block
    const size_t base = (size_t)bh * TT * HD_;

    const float sigma = *sigp;
    const float c1    = -sigma * 1.4426950408889634f;   // -sigma*log2(e)
    const float m2c1  = -2.0f * c1;

    // Load K tile (natural layout, coalesced)
#pragma unroll
    for (int p = 0; p < 4; p++) {
        int id = tid + p * 256;     // 0..1023 float4 ids
        int r  = id >> 4;           // 0..63
        int c4 = id & 15;
        *(float4*)(&Kt[r*64 + c4*4]) =
            *(const float4*)(g_k + base + (size_t)(i0 + r) * HD_ + c4 * 4);
    }

    float knc1[4];
#pragma unroll
    for (int r = 0; r < 4; r++)
        knc1[r] = c1 * g_kn[bh * TT + i0 + ty*4 + r];

    float acc[4][4];
#pragma unroll
    for (int r = 0; r < 4; r++)
#pragma unroll
        for (int c = 0; c < 4; c++) acc[r][c] = 0.f;

    for (int j0 = 0; j0 < TT; j0 += 64) {
        __syncthreads();   // prev O-GEMM done reading QV/P before overwrite

        // Load Q tile transposed (swizzled): QV[qswz(d, j)]
#pragma unroll
        for (int p = 0; p < 4; p++) {
            int id = tid + p * 256;
            int r  = id >> 4;       // j 0..63
            int c4 = id & 15;
            float4 v = *(const float4*)(g_q + base + (size_t)(j0 + r) * HD_ + c4 * 4);
            QV[qswz(c4*4+0, r)] = v.x;
            QV[qswz(c4*4+1, r)] = v.y;
            QV[qswz(c4*4+2, r)] = v.z;
            QV[qswz(c4*4+3, r)] = v.w;
        }
        float qnc1[4];
#pragma unroll
        for (int c = 0; c < 4; c++)
            qnc1[c] = c1 * g_qn[bh * TT + j0 + tx*4 + c];
        __syncthreads();

        // S[i][j] = sum_d K[i][d] * Q[j][d]
        float s[4][4];
#pragma unroll
        for (int r = 0; r < 4; r++)
#pragma unroll
            for (int c = 0; c < 4; c++) s[r][c] = 0.f;
#pragma unroll 8
        for (int d = 0; d < 64; d++) {
            float a[4], b[4];
#pragma unroll
            for (int r = 0; r < 4; r++) a[r] = Kt[(ty*4+r)*64 + d];
#pragma unroll
            for (int c = 0; c < 4; c++) b[c] = QV[qswz(d, tx*4 + c)];
#pragma unroll
            for (int r = 0; r < 4; r++)
#pragma unroll
                for (int c = 0; c < 4; c++)
                    s[r][c] = fmaf(a[r], b[c], s[r][c]);
        }
        __syncthreads();   // all threads done reading Q before V overwrites

        // P = exp(-dist2*sigma) ; overlap with V tile load into QV
#pragma unroll
        for (int r = 0; r < 4; r++)
#pragma unroll
            for (int c = 0; c < 4; c++) {
                float t = fmaf(m2c1, s[r][c], knc1[r] + qnc1[c]);
                P[(ty*4+r)*64 + tx*4 + c] = fexp2(t);
            }
#pragma unroll
        for (int p = 0; p < 4; p++) {
            int id = tid + p * 256;
            int r  = id >> 4;
            int c4 = id & 15;
            *(float4*)(&QV[r*64 + c4*4]) =
                *(const float4*)(g_v + base + (size_t)(j0 + r) * HD_ + c4 * 4);
        }
        __syncthreads();

        // O[i][d] += sum_j P[i][j] * V[j][d]
#pragma unroll 8
        for (int jj = 0; jj < 64; jj++) {
            float pv[4], vv[4];
#pragma unroll
            for (int r = 0; r < 4; r++) pv[r] = P[(ty*4+r)*64 + jj];
#pragma unroll
            for (int c = 0; c < 4; c++) vv[c] = QV[jj*64 + tx*4 + c];
#pragma unroll
            for (int r = 0; r < 4; r++)
#pragma unroll
                for (int c = 0; c < 4; c++)
                    acc[r][c] = fmaf(pv[r], vv[c], acc[r][c]);
        }
    }

    // Write in (B, T, DIM) layout: g_attn[(b*T + i)*1024 + h*64 + d]
    const int b_ = bh >> 4;
    const int h  = bh & 15;
#pragma unroll
    for (int r = 0; r < 4; r++) {
        size_t o = ((size_t)b_ * TT + i0 + ty*4 + r) * DIM_ + h * HD_ + tx*4;
        float4 v = make_float4(acc[r][0], acc[r][1], acc[r][2], acc[r][3]);
        *(float4*)(g_attn + o) = v;
    }
}

// ---------------------------------------------------------------------------
// kernel_launch
// Inputs: x, Wqkv, bqkv, r_sigma, Wproj, bproj (metadata order)
// ---------------------------------------------------------------------------
extern "C" void kernel_launch(void* const* d_in, const int* in_sizes, int n_in,
                              void* d_out, int out_size)
{
    (void)in_sizes; (void)n_in; (void)out_size;
    const float* x     = (const float*)d_in[0];
    const float* Wqkv  = (const float*)d_in[1];
    const float* bqkv  = (const float*)d_in[2];
    const float* sig   = (const float*)d_in[3];
    const float* Wproj = (const float*)d_in[4];
    const float* bproj = (const float*)d_in[5];
    float* out = (float*)d_out;

    // 1) QKV GEMM with (B,H,T,HD) scatter
    sgemm_kernel<0><<<dim3(N1/128, M1/128), 256>>>(x, Wqkv, bqkv, nullptr, N1);

    // 2) Row norms
    norms_kernel<<<(NROWS * 32) / 256, 256>>>();

    // 3) Attention (48KB static smem, no attribute calls)
    attn_kernel<<<dim3(TT/64, BB*HH), 256>>>(sig);

    // 4) Projection GEMM + bias -> d_out
    sgemm_kernel<1><<<dim3(CC/128, M1/128), 256>>>(nullptr, Wproj, bproj, out, CC);
}

// round 6
// speedup vs baseline: 1.7404x; 1.7404x over previous
#include <cuda_runtime.h>
#include <cuda_bf16.h>
#include <cstdint>
#include <cstddef>

#define BB   2
#define TT   2048
#define CC   1024
#define DIM_ 1024
#define HH   16
#define HD_  64
#define M1   (BB*TT)        // 4096
#define N1   (3*DIM_)       // 3072
#define KDIM 1024
#define NROWS (BB*HH*TT)    // 65536

typedef __nv_bfloat16  bf16;
typedef __nv_bfloat162 bf162;

// ---------------------------------------------------------------------------
// Scratch — EXACTLY 64.5 MiB total (round-2-proven footprint)
// q,k: hi/lo bf16 [bh][t][d]; v: hi/lo bf16 TRANSPOSED [bh][d][t]
// ---------------------------------------------------------------------------
__device__ __align__(16) bf16 g_qh[(size_t)NROWS*HD_], g_ql[(size_t)NROWS*HD_];   // 16 MiB
__device__ __align__(16) bf16 g_kh[(size_t)NROWS*HD_], g_kl[(size_t)NROWS*HD_];   // 16 MiB
__device__ __align__(16) bf16 g_vth[(size_t)NROWS*HD_], g_vtl[(size_t)NROWS*HD_]; // 16 MiB
__device__ float g_attn[(size_t)M1*DIM_];                                          // 16 MiB
__device__ float g_qn[NROWS], g_kn[NROWS];                                         // 0.5 MiB

// ---------------------------------------------------------------------------
// Helpers
// ---------------------------------------------------------------------------
__device__ __forceinline__ void bsplit(float x, bf16 &h, bf16 &l) {
    h = __float2bfloat16_rn(x);
    l = __float2bfloat16_rn(x - __bfloat162float(h));
}
__device__ __forceinline__ unsigned packb(bf16 a, bf16 b) {
    bf162 t; t.x = a; t.y = b;
    return *reinterpret_cast<unsigned*>(&t);
}
__device__ __forceinline__ void mma_bf16(float* c,
    unsigned a0, unsigned a1, unsigned a2, unsigned a3,
    unsigned b0, unsigned b1)
{
    asm volatile(
        "mma.sync.aligned.m16n8k16.row.col.f32.bf16.bf16.f32 "
        "{%0,%1,%2,%3},{%4,%5,%6,%7},{%8,%9},{%0,%1,%2,%3};\n"
        : "+f"(c[0]), "+f"(c[1]), "+f"(c[2]), "+f"(c[3])
        : "r"(a0), "r"(a1), "r"(a2), "r"(a3), "r"(b0), "r"(b1));
}
// Fast 2^t (FMA pipe only), max rel err ~8e-6
__device__ __forceinline__ float fexp2(float t) {
    t = fmaxf(t, -125.0f);
    float fi = floorf(t);
    float f  = t - fi;
    float p  = 1.5403530e-4f;
    p = fmaf(p, f, 1.3333558e-3f);
    p = fmaf(p, f, 9.6181291e-3f);
    p = fmaf(p, f, 5.5504109e-2f);
    p = fmaf(p, f, 2.4022651e-1f);
    p = fmaf(p, f, 6.9314718e-1f);
    p = fmaf(p, f, 1.0f);
    return p * __int_as_float(((int)fi + 127) << 23);
}

// ---------------------------------------------------------------------------
// fp32 SGEMM 128x128x16 (round-2 proven). MODE 0: QKV -> hi/lo bf16 scatter
// (q,k natural; v transposed). MODE 1: proj -> fp32 d_out.
// ---------------------------------------------------------------------------
template <int MODE>
__global__ void __launch_bounds__(256)
sgemm_kernel(const float* __restrict__ A_in,
             const float* __restrict__ Bm,
             const float* __restrict__ bias,
             float* __restrict__ Cout,
             int Ncols)
{
    __shared__ float As[16][128];
    __shared__ float Bs[16][128];

    const float* A = (MODE == 0) ? A_in : g_attn;

    const int tid = threadIdx.x;
    const int m0  = blockIdx.y * 128;
    const int n0  = blockIdx.x * 128;
    const int ty  = tid >> 4;
    const int tx  = tid & 15;

    float acc[8][8];
#pragma unroll
    for (int i = 0; i < 8; i++)
#pragma unroll
        for (int j = 0; j < 8; j++) acc[i][j] = 0.f;

    for (int k0 = 0; k0 < KDIM; k0 += 16) {
#pragma unroll
        for (int p = 0; p < 2; p++) {
            int id = tid + p * 256;
            int r  = id >> 2;
            int c4 = id & 3;
            float4 v = *(const float4*)(A + (size_t)(m0 + r) * KDIM + k0 + c4 * 4);
            As[c4*4+0][r] = v.x; As[c4*4+1][r] = v.y;
            As[c4*4+2][r] = v.z; As[c4*4+3][r] = v.w;
        }
#pragma unroll
        for (int p = 0; p < 2; p++) {
            int id = tid + p * 256;
            int r  = id >> 5;
            int c4 = id & 31;
            *(float4*)(&Bs[r][c4*4]) =
                *(const float4*)(Bm + (size_t)(k0 + r) * Ncols + n0 + c4 * 4);
        }
        __syncthreads();

#pragma unroll
        for (int kk = 0; kk < 16; kk++) {
            float a[8], b[8];
#pragma unroll
            for (int i = 0; i < 8; i++) a[i] = As[kk][ty*8 + i];
#pragma unroll
            for (int j = 0; j < 8; j++) b[j] = Bs[kk][tx*8 + j];
#pragma unroll
            for (int i = 0; i < 8; i++)
#pragma unroll
                for (int j = 0; j < 8; j++)
                    acc[i][j] = fmaf(a[i], b[j], acc[i][j]);
        }
        __syncthreads();
    }

#pragma unroll
    for (int i = 0; i < 8; i++) {
        int m  = m0 + ty*8 + i;
        int b_ = m >> 11;
        int t  = m & 2047;
#pragma unroll
        for (int j = 0; j < 8; j++) {
            int n = n0 + tx*8 + j;
            float val = acc[i][j] + bias[n];
            if (MODE == 0) {
                int s = n >> 10;          // 0:q 1:k 2:v
                int h = (n >> 6) & 15;
                int d = n & 63;
                int bh = b_ * HH + h;
                bf16 hi, lo; bsplit(val, hi, lo);
                if (s == 0) {
                    size_t idx = ((size_t)bh * TT + t) * HD_ + d;
                    g_qh[idx] = hi; g_ql[idx] = lo;
                } else if (s == 1) {
                    size_t idx = ((size_t)bh * TT + t) * HD_ + d;
                    g_kh[idx] = hi; g_kl[idx] = lo;
                } else {
                    size_t idx = ((size_t)bh * HD_ + d) * TT + t;  // transposed
                    g_vth[idx] = hi; g_vtl[idx] = lo;
                }
            } else {
                Cout[(size_t)m * Ncols + n] = val;
            }
        }
    }
}

// ---------------------------------------------------------------------------
// Row norms from hi/lo bf16 q,k — one warp per (b,h,t) row
// ---------------------------------------------------------------------------
__global__ void norms_kernel()
{
    int w    = (blockIdx.x * blockDim.x + threadIdx.x) >> 5;
    int lane = threadIdx.x & 31;
    size_t o = (size_t)w * HD_ + lane * 2;
    bf162 qh = *reinterpret_cast<bf162*>(g_qh + o);
    bf162 ql = *reinterpret_cast<bf162*>(g_ql + o);
    bf162 kh = *reinterpret_cast<bf162*>(g_kh + o);
    bf162 kl = *reinterpret_cast<bf162*>(g_kl + o);
    float q0 = __bfloat162float(qh.x) + __bfloat162float(ql.x);
    float q1 = __bfloat162float(qh.y) + __bfloat162float(ql.y);
    float k0 = __bfloat162float(kh.x) + __bfloat162float(kl.x);
    float k1 = __bfloat162float(kh.y) + __bfloat162float(kl.y);
    float sq = q0*q0 + q1*q1;
    float sk = k0*k0 + k1*k1;
#pragma unroll
    for (int off = 16; off; off >>= 1) {
        sq += __shfl_xor_sync(0xFFFFFFFFu, sq, off);
        sk += __shfl_xor_sync(0xFFFFFFFFu, sk, off);
    }
    if (lane == 0) { g_qn[w] = sq; g_kn[w] = sk; }
}

// ---------------------------------------------------------------------------
// Attention: CTA 128 thr (4 warps), i-tile 64 (warp = 16 rows), j-tiles of 64.
// S = K·Q^T (3-pass hi/lo MMA) -> P via fexp2 (C-frag -> A-frag in registers)
// -> O += P·V (3-pass MMA). V is pre-transposed in GLOBAL ([d][t]), so both
// Q and V^T tile loads are coalesced and frag reads are single LDS32.
// Output: fp32 g_attn in (B,T,DIM) layout.
// ---------------------------------------------------------------------------
__global__ void __launch_bounds__(128)
attn_mma_kernel(const float* __restrict__ sigp)
{
    __shared__ __align__(16) bf16 Ksh[64][72], Ksl[64][72];
    __shared__ __align__(16) bf16 QVh[64][72], QVl[64][72];
    __shared__ float qns[64];

    const int tid  = threadIdx.x;
    const int w    = tid >> 5, lane = tid & 31;
    const int g    = lane >> 2, t = lane & 3;
    const int bh   = blockIdx.y;
    const int i0   = blockIdx.x * 64;
    const size_t base = (size_t)bh * TT * HD_;   // same total for [t][d] and [d][t]

    const float sigma = *sigp;
    const float c1    = -sigma * 1.4426950408889634f;
    const float m2c1  = -2.0f * c1;

    // K tile (persistent): [i][d]
#pragma unroll
    for (int p = 0; p < 4; p++) {
        int id = tid + p * 128;
        int r  = id >> 3, qd = id & 7;
        size_t off = base + (size_t)(i0 + r) * HD_ + qd * 8;
        *reinterpret_cast<uint4*>(&Ksh[r][qd*8]) = *reinterpret_cast<const uint4*>(g_kh + off);
        *reinterpret_cast<uint4*>(&Ksl[r][qd*8]) = *reinterpret_cast<const uint4*>(g_kl + off);
    }
    const float knc0 = c1 * g_kn[bh * TT + i0 + 16*w + g];
    const float knc8 = c1 * g_kn[bh * TT + i0 + 16*w + 8 + g];

    float O[8][4];
#pragma unroll
    for (int nf = 0; nf < 8; nf++)
#pragma unroll
        for (int r = 0; r < 4; r++) O[nf][r] = 0.f;

    for (int j0 = 0; j0 < TT; j0 += 64) {
        __syncthreads();   // prev iter done reading QV
        // Q tile [j][d] — coalesced
#pragma unroll
        for (int p = 0; p < 4; p++) {
            int id = tid + p * 128;
            int r  = id >> 3, qd = id & 7;
            size_t off = base + (size_t)(j0 + r) * HD_ + qd * 8;
            *reinterpret_cast<uint4*>(&QVh[r][qd*8]) = *reinterpret_cast<const uint4*>(g_qh + off);
            *reinterpret_cast<uint4*>(&QVl[r][qd*8]) = *reinterpret_cast<const uint4*>(g_ql + off);
        }
        if (tid < 64) qns[tid] = c1 * g_qn[bh * TT + j0 + tid];
        __syncthreads();

        // S[i][j] GEMM: A = K rows, B = Q (col-major over d)
        float S[8][4];
#pragma unroll
        for (int nf = 0; nf < 8; nf++)
#pragma unroll
            for (int r = 0; r < 4; r++) S[nf][r] = 0.f;
#pragma unroll
        for (int kf = 0; kf < 4; kf++) {
            const int row = 16 * w;
            const int c0  = kf * 16 + 2 * t;
            unsigned ah0 = *reinterpret_cast<unsigned*>(&Ksh[row+g  ][c0  ]);
            unsigned ah1 = *reinterpret_cast<unsigned*>(&Ksh[row+g+8][c0  ]);
            unsigned ah2 = *reinterpret_cast<unsigned*>(&Ksh[row+g  ][c0+8]);
            unsigned ah3 = *reinterpret_cast<unsigned*>(&Ksh[row+g+8][c0+8]);
            unsigned al0 = *reinterpret_cast<unsigned*>(&Ksl[row+g  ][c0  ]);
            unsigned al1 = *reinterpret_cast<unsigned*>(&Ksl[row+g+8][c0  ]);
            unsigned al2 = *reinterpret_cast<unsigned*>(&Ksl[row+g  ][c0+8]);
            unsigned al3 = *reinterpret_cast<unsigned*>(&Ksl[row+g+8][c0+8]);
#pragma unroll
            for (int nf = 0; nf < 8; nf++) {
                unsigned bh0 = *reinterpret_cast<unsigned*>(&QVh[nf*8+g][c0  ]);
                unsigned bh1 = *reinterpret_cast<unsigned*>(&QVh[nf*8+g][c0+8]);
                unsigned bl0 = *reinterpret_cast<unsigned*>(&QVl[nf*8+g][c0  ]);
                unsigned bl1 = *reinterpret_cast<unsigned*>(&QVl[nf*8+g][c0+8]);
                mma_bf16(S[nf], ah0, ah1, ah2, ah3, bh0, bh1);
                mma_bf16(S[nf], ah0, ah1, ah2, ah3, bl0, bl1);
                mma_bf16(S[nf], al0, al1, al2, al3, bh0, bh1);
            }
        }

        // P = exp kernel; repack S C-frags -> PV A-frags (pure in-thread)
        unsigned Ph[4][4], Pl[4][4];
#pragma unroll
        for (int nf = 0; nf < 8; nf++) {
            float qn0 = qns[nf*8 + 2*t], qn1 = qns[nf*8 + 2*t + 1];
            float p00 = fexp2(fmaf(m2c1, S[nf][0], knc0 + qn0));
            float p01 = fexp2(fmaf(m2c1, S[nf][1], knc0 + qn1));
            float p10 = fexp2(fmaf(m2c1, S[nf][2], knc8 + qn0));
            float p11 = fexp2(fmaf(m2c1, S[nf][3], knc8 + qn1));
            bf16 h00,l00,h01,l01,h10,l10,h11,l11;
            bsplit(p00,h00,l00); bsplit(p01,h01,l01);
            bsplit(p10,h10,l10); bsplit(p11,h11,l11);
            int kf = nf >> 1;
            if ((nf & 1) == 0) {
                Ph[kf][0] = packb(h00,h01); Ph[kf][1] = packb(h10,h11);
                Pl[kf][0] = packb(l00,l01); Pl[kf][1] = packb(l10,l11);
            } else {
                Ph[kf][2] = packb(h00,h01); Ph[kf][3] = packb(h10,h11);
                Pl[kf][2] = packb(l00,l01); Pl[kf][3] = packb(l10,l11);
            }
        }
        __syncthreads();   // done reading Q from QV

        // V^T tile [d][j] — coalesced load from pre-transposed global
#pragma unroll
        for (int p = 0; p < 4; p++) {
            int id = tid + p * 128;
            int r  = id >> 3, qd = id & 7;          // r = d-local, qd = j-segment
            size_t off = base + (size_t)r * TT + j0 + qd * 8;
            *reinterpret_cast<uint4*>(&QVh[r][qd*8]) = *reinterpret_cast<const uint4*>(g_vth + off);
            *reinterpret_cast<uint4*>(&QVl[r][qd*8]) = *reinterpret_cast<const uint4*>(g_vtl + off);
        }
        __syncthreads();

        // O += P @ V   (A = P in regs; B = V^T[d][j], col-major over j)
#pragma unroll
        for (int kf = 0; kf < 4; kf++) {
            const int jc = kf * 8 + t;              // 32-bit word index: j-pair c0/2
#pragma unroll
            for (int nf = 0; nf < 8; nf++) {
                const unsigned* rowh = reinterpret_cast<const unsigned*>(&QVh[nf*8+g][0]);
                const unsigned* rowl = reinterpret_cast<const unsigned*>(&QVl[nf*8+g][0]);
                unsigned bh0 = rowh[jc];
                unsigned bh1 = rowh[jc + 4];
                unsigned bl0 = rowl[jc];
                unsigned bl1 = rowl[jc + 4];
                mma_bf16(O[nf], Ph[kf][0],Ph[kf][1],Ph[kf][2],Ph[kf][3], bh0, bh1);
                mma_bf16(O[nf], Ph[kf][0],Ph[kf][1],Ph[kf][2],Ph[kf][3], bl0, bl1);
                mma_bf16(O[nf], Pl[kf][0],Pl[kf][1],Pl[kf][2],Pl[kf][3], bh0, bh1);
            }
        }
    }

    // Write fp32 attn-out in (B, T, DIM) layout
    const int b_ = bh >> 4;
    const int h  = bh & 15;
#pragma unroll
    for (int nf = 0; nf < 8; nf++) {
        int d  = nf * 8 + 2 * t;
        int iA = i0 + 16*w + g;
        int iB = iA + 8;
        size_t oA = ((size_t)b_ * TT + iA) * DIM_ + h * HD_ + d;
        size_t oB = ((size_t)b_ * TT + iB) * DIM_ + h * HD_ + d;
        *reinterpret_cast<float2*>(g_attn + oA) = make_float2(O[nf][0], O[nf][1]);
        *reinterpret_cast<float2*>(g_attn + oB) = make_float2(O[nf][2], O[nf][3]);
    }
}

// ---------------------------------------------------------------------------
// kernel_launch — inputs: x, Wqkv, bqkv, r_sigma, Wproj, bproj
// ---------------------------------------------------------------------------
extern "C" void kernel_launch(void* const* d_in, const int* in_sizes, int n_in,
                              void* d_out, int out_size)
{
    (void)in_sizes; (void)n_in; (void)out_size;
    const float* x     = (const float*)d_in[0];
    const float* Wqkv  = (const float*)d_in[1];
    const float* bqkv  = (const float*)d_in[2];
    const float* sig   = (const float*)d_in[3];
    const float* Wproj = (const float*)d_in[4];
    const float* bproj = (const float*)d_in[5];
    float* out = (float*)d_out;

    // 1) QKV GEMM (fp32 SIMT) -> hi/lo bf16 q,k + transposed v
    sgemm_kernel<0><<<dim3(N1/128, M1/128), 256>>>(x, Wqkv, bqkv, nullptr, N1);

    // 2) Row norms
    norms_kernel<<<(NROWS * 32) / 256, 256>>>();

    // 3) Attention (tensor-core MMA, hi/lo 3-pass)
    attn_mma_kernel<<<dim3(TT/64, BB*HH), 128>>>(sig);

    // 4) Projection GEMM (fp32 SIMT) -> d_out
    sgemm_kernel<1><<<dim3(CC/128, M1/128), 256>>>(nullptr, Wproj, bproj, out, CC);
}

// round 7
// speedup vs baseline: 2.6660x; 1.5319x over previous
#include <cuda_runtime.h>
#include <cuda_bf16.h>
#include <cstdint>
#include <cstddef>

#define BB   2
#define TT   2048
#define CC   1024
#define DIM_ 1024
#define HH   16
#define HD_  64
#define M1   (BB*TT)        // 4096
#define N1   (3*DIM_)       // 3072
#define KDIM 1024
#define NROWS (BB*HH*TT)    // 65536

typedef __nv_bfloat16  bf16;
typedef __nv_bfloat162 bf162;

// ---------------------------------------------------------------------------
// Scratch — EXACTLY 64.5 MiB (proven footprint). No other globals.
// ---------------------------------------------------------------------------
__device__ __align__(16) bf16 g_qh[(size_t)NROWS*HD_], g_ql[(size_t)NROWS*HD_];
__device__ __align__(16) bf16 g_kh[(size_t)NROWS*HD_], g_kl[(size_t)NROWS*HD_];
__device__ __align__(16) bf16 g_vth[(size_t)NROWS*HD_], g_vtl[(size_t)NROWS*HD_];
__device__ float g_attn[(size_t)M1*DIM_];
__device__ float g_qn[NROWS], g_kn[NROWS];

// ---------------------------------------------------------------------------
// Helpers
// ---------------------------------------------------------------------------
__device__ __forceinline__ void bsplit(float x, bf16 &h, bf16 &l) {
    h = __float2bfloat16_rn(x);
    l = __float2bfloat16_rn(x - __bfloat162float(h));
}
__device__ __forceinline__ unsigned packb(bf16 a, bf16 b) {
    bf162 t; t.x = a; t.y = b;
    return *reinterpret_cast<unsigned*>(&t);
}
__device__ __forceinline__ void mma_bf16(float* c,
    unsigned a0, unsigned a1, unsigned a2, unsigned a3,
    unsigned b0, unsigned b1)
{
    asm volatile(
        "mma.sync.aligned.m16n8k16.row.col.f32.bf16.bf16.f32 "
        "{%0,%1,%2,%3},{%4,%5,%6,%7},{%8,%9},{%0,%1,%2,%3};\n"
        : "+f"(c[0]), "+f"(c[1]), "+f"(c[2]), "+f"(c[3])
        : "r"(a0), "r"(a1), "r"(a2), "r"(a3), "r"(b0), "r"(b1));
}
// Fast 2^t (FMA pipe only), max rel err ~8e-6
__device__ __forceinline__ float fexp2(float t) {
    t = fmaxf(t, -125.0f);
    float fi = floorf(t);
    float f  = t - fi;
    float p  = 1.5403530e-4f;
    p = fmaf(p, f, 1.3333558e-3f);
    p = fmaf(p, f, 9.6181291e-3f);
    p = fmaf(p, f, 5.5504109e-2f);
    p = fmaf(p, f, 2.4022651e-1f);
    p = fmaf(p, f, 6.9314718e-1f);
    p = fmaf(p, f, 1.0f);
    return p * __int_as_float(((int)fi + 127) << 23);
}

// ---------------------------------------------------------------------------
// Tensor-core GEMM with on-the-fly fp32 -> hi/lo bf16 split (3-pass MMA).
// C[M][N] = A(fp32,[M][K]) @ B(fp32,[K][N]) + bias.
// CTA 128m x 64n, 8 warps (4m x 2n), warp tile 32x32, k-chunk 32.
// MODE 0: QKV -> scatter hi/lo bf16 (q,k natural; v transposed [d][t])
// MODE 1: proj -> fp32 d_out
// ---------------------------------------------------------------------------
template <int MODE>
__global__ void __launch_bounds__(256)
mma_gemm(const float* __restrict__ A_g, const float* __restrict__ Bm,
         const float* __restrict__ bias, float* __restrict__ Cout, int Ncols)
{
    __shared__ __align__(16) bf16 Ash[128][36], Asl[128][36];
    __shared__ __align__(16) bf16 Bsh[64][36],  Bsl[64][36];

    const float* A = (MODE == 0) ? A_g : g_attn;
    const int tid = threadIdx.x;
    const int m0  = blockIdx.y * 128;
    const int n0  = blockIdx.x * 64;
    const int w   = tid >> 5, lane = tid & 31;
    const int wm  = w >> 1,  wn  = w & 1;
    const int g   = lane >> 2, t = lane & 3;

    const int bn  = tid & 63;      // B-fill: n within tile
    const int bkh = tid >> 6;      // B-fill: k-octet 0..3

    float C[2][4][4];
#pragma unroll
    for (int mf = 0; mf < 2; mf++)
#pragma unroll
        for (int nf = 0; nf < 4; nf++)
#pragma unroll
            for (int r = 0; r < 4; r++) C[mf][nf][r] = 0.f;

    for (int k0 = 0; k0 < KDIM; k0 += 32) {
        __syncthreads();
        // A tile 128x32: fp32 float4 loads (coalesced), split to hi/lo bf16
#pragma unroll
        for (int p = 0; p < 4; p++) {
            int id = tid + p * 256;
            int r  = id >> 3, c4 = id & 7;
            float4 v = *(const float4*)(A + (size_t)(m0 + r) * KDIM + k0 + c4 * 4);
            bf16 h0,l0,h1,l1,h2,l2,h3,l3;
            bsplit(v.x,h0,l0); bsplit(v.y,h1,l1);
            bsplit(v.z,h2,l2); bsplit(v.w,h3,l3);
            *reinterpret_cast<uint2*>(&Ash[r][c4*4]) = make_uint2(packb(h0,h1), packb(h2,h3));
            *reinterpret_cast<uint2*>(&Asl[r][c4*4]) = make_uint2(packb(l0,l1), packb(l2,l3));
        }
        // B tile 32x64: fp32 [k][n] loads (n-coalesced), transpose+split -> [n][k]
#pragma unroll
        for (int kk2 = 0; kk2 < 4; kk2++) {
            int k = bkh * 8 + kk2 * 2;
            float v0 = Bm[(size_t)(k0 + k    ) * Ncols + n0 + bn];
            float v1 = Bm[(size_t)(k0 + k + 1) * Ncols + n0 + bn];
            bf16 h0,l0,h1,l1;
            bsplit(v0,h0,l0); bsplit(v1,h1,l1);
            *reinterpret_cast<unsigned*>(&Bsh[bn][k]) = packb(h0,h1);
            *reinterpret_cast<unsigned*>(&Bsl[bn][k]) = packb(l0,l1);
        }
        __syncthreads();

#pragma unroll
        for (int ks = 0; ks < 2; ks++) {
            const int c0 = ks * 16 + 2 * t;
            unsigned ah[2][4], al[2][4];
#pragma unroll
            for (int mf = 0; mf < 2; mf++) {
                int row = wm * 32 + mf * 16;
                ah[mf][0] = *reinterpret_cast<unsigned*>(&Ash[row+g  ][c0  ]);
                ah[mf][1] = *reinterpret_cast<unsigned*>(&Ash[row+g+8][c0  ]);
                ah[mf][2] = *reinterpret_cast<unsigned*>(&Ash[row+g  ][c0+8]);
                ah[mf][3] = *reinterpret_cast<unsigned*>(&Ash[row+g+8][c0+8]);
                al[mf][0] = *reinterpret_cast<unsigned*>(&Asl[row+g  ][c0  ]);
                al[mf][1] = *reinterpret_cast<unsigned*>(&Asl[row+g+8][c0  ]);
                al[mf][2] = *reinterpret_cast<unsigned*>(&Asl[row+g  ][c0+8]);
                al[mf][3] = *reinterpret_cast<unsigned*>(&Asl[row+g+8][c0+8]);
            }
#pragma unroll
            for (int nf = 0; nf < 4; nf++) {
                int col = wn * 32 + nf * 8;
                unsigned bh0 = *reinterpret_cast<unsigned*>(&Bsh[col+g][c0  ]);
                unsigned bh1 = *reinterpret_cast<unsigned*>(&Bsh[col+g][c0+8]);
                unsigned bl0 = *reinterpret_cast<unsigned*>(&Bsl[col+g][c0  ]);
                unsigned bl1 = *reinterpret_cast<unsigned*>(&Bsl[col+g][c0+8]);
#pragma unroll
                for (int mf = 0; mf < 2; mf++) {
                    mma_bf16(C[mf][nf], ah[mf][0],ah[mf][1],ah[mf][2],ah[mf][3], bh0, bh1);
                    mma_bf16(C[mf][nf], ah[mf][0],ah[mf][1],ah[mf][2],ah[mf][3], bl0, bl1);
                    mma_bf16(C[mf][nf], al[mf][0],al[mf][1],al[mf][2],al[mf][3], bh0, bh1);
                }
            }
        }
    }

    // Epilogue
#pragma unroll
    for (int mf = 0; mf < 2; mf++) {
#pragma unroll
        for (int nf = 0; nf < 4; nf++) {
            int n  = n0 + wn * 32 + nf * 8 + 2 * t;
            float b0 = bias[n], b1 = bias[n + 1];
            int mA = m0 + wm * 32 + mf * 16 + g;
            int mB = mA + 8;
            float v00 = C[mf][nf][0] + b0, v01 = C[mf][nf][1] + b1;
            float v10 = C[mf][nf][2] + b0, v11 = C[mf][nf][3] + b1;
            if (MODE == 0) {
                int s = n >> 10, h = (n >> 6) & 15, d = n & 63;
                int bhA = (mA >> 11) * HH + h, tA = mA & 2047;
                int bhB = (mB >> 11) * HH + h, tB = mB & 2047;
                bf16 h00,l00,h01,l01,h10,l10,h11,l11;
                bsplit(v00,h00,l00); bsplit(v01,h01,l01);
                bsplit(v10,h10,l10); bsplit(v11,h11,l11);
                if (s == 2) {
                    // v transposed: [bh][d][t]
                    size_t iA0 = ((size_t)bhA * HD_ + d    ) * TT + tA;
                    size_t iA1 = ((size_t)bhA * HD_ + d + 1) * TT + tA;
                    size_t iB0 = ((size_t)bhB * HD_ + d    ) * TT + tB;
                    size_t iB1 = ((size_t)bhB * HD_ + d + 1) * TT + tB;
                    g_vth[iA0] = h00; g_vtl[iA0] = l00;
                    g_vth[iA1] = h01; g_vtl[iA1] = l01;
                    g_vth[iB0] = h10; g_vtl[iB0] = l10;
                    g_vth[iB1] = h11; g_vtl[iB1] = l11;
                } else {
                    bf16* ph = (s == 0) ? g_qh : g_kh;
                    bf16* pl = (s == 0) ? g_ql : g_kl;
                    size_t iA = ((size_t)bhA * TT + tA) * HD_ + d;
                    size_t iB = ((size_t)bhB * TT + tB) * HD_ + d;
                    *reinterpret_cast<unsigned*>(ph + iA) = packb(h00, h01);
                    *reinterpret_cast<unsigned*>(pl + iA) = packb(l00, l01);
                    *reinterpret_cast<unsigned*>(ph + iB) = packb(h10, h11);
                    *reinterpret_cast<unsigned*>(pl + iB) = packb(l10, l11);
                }
            } else {
                *reinterpret_cast<float2*>(&Cout[(size_t)mA * Ncols + n]) = make_float2(v00, v01);
                *reinterpret_cast<float2*>(&Cout[(size_t)mB * Ncols + n]) = make_float2(v10, v11);
            }
        }
    }
}

// ---------------------------------------------------------------------------
// Row norms from hi/lo bf16 q,k — one warp per (b,h,t) row  (round-6 proven)
// ---------------------------------------------------------------------------
__global__ void norms_kernel()
{
    int w    = (blockIdx.x * blockDim.x + threadIdx.x) >> 5;
    int lane = threadIdx.x & 31;
    size_t o = (size_t)w * HD_ + lane * 2;
    bf162 qh = *reinterpret_cast<bf162*>(g_qh + o);
    bf162 ql = *reinterpret_cast<bf162*>(g_ql + o);
    bf162 kh = *reinterpret_cast<bf162*>(g_kh + o);
    bf162 kl = *reinterpret_cast<bf162*>(g_kl + o);
    float q0 = __bfloat162float(qh.x) + __bfloat162float(ql.x);
    float q1 = __bfloat162float(qh.y) + __bfloat162float(ql.y);
    float k0 = __bfloat162float(kh.x) + __bfloat162float(kl.x);
    float k1 = __bfloat162float(kh.y) + __bfloat162float(kl.y);
    float sq = q0*q0 + q1*q1;
    float sk = k0*k0 + k1*k1;
#pragma unroll
    for (int off = 16; off; off >>= 1) {
        sq += __shfl_xor_sync(0xFFFFFFFFu, sq, off);
        sk += __shfl_xor_sync(0xFFFFFFFFu, sk, off);
    }
    if (lane == 0) { g_qn[w] = sq; g_kn[w] = sk; }
}

// ---------------------------------------------------------------------------
// Attention (round-6 proven, unchanged): CTA 128 thr, i-tile 64, j-tiles 64.
// S = K·Q^T (3-pass MMA) -> P = fexp2 (reg relayout) -> O += P·V (3-pass MMA)
// V pre-transposed in global ([d][t]); fp32 out to g_attn (B,T,DIM).
// ---------------------------------------------------------------------------
__global__ void __launch_bounds__(128)
attn_mma_kernel(const float* __restrict__ sigp)
{
    __shared__ __align__(16) bf16 Ksh[64][72], Ksl[64][72];
    __shared__ __align__(16) bf16 QVh[64][72], QVl[64][72];
    __shared__ float qns[64];

    const int tid  = threadIdx.x;
    const int w    = tid >> 5, lane = tid & 31;
    const int g    = lane >> 2, t = lane & 3;
    const int bh   = blockIdx.y;
    const int i0   = blockIdx.x * 64;
    const size_t base = (size_t)bh * TT * HD_;

    const float sigma = *sigp;
    const float c1    = -sigma * 1.4426950408889634f;
    const float m2c1  = -2.0f * c1;

#pragma unroll
    for (int p = 0; p < 4; p++) {
        int id = tid + p * 128;
        int r  = id >> 3, qd = id & 7;
        size_t off = base + (size_t)(i0 + r) * HD_ + qd * 8;
        *reinterpret_cast<uint4*>(&Ksh[r][qd*8]) = *reinterpret_cast<const uint4*>(g_kh + off);
        *reinterpret_cast<uint4*>(&Ksl[r][qd*8]) = *reinterpret_cast<const uint4*>(g_kl + off);
    }
    const float knc0 = c1 * g_kn[bh * TT + i0 + 16*w + g];
    const float knc8 = c1 * g_kn[bh * TT + i0 + 16*w + 8 + g];

    float O[8][4];
#pragma unroll
    for (int nf = 0; nf < 8; nf++)
#pragma unroll
        for (int r = 0; r < 4; r++) O[nf][r] = 0.f;

    for (int j0 = 0; j0 < TT; j0 += 64) {
        __syncthreads();
#pragma unroll
        for (int p = 0; p < 4; p++) {
            int id = tid + p * 128;
            int r  = id >> 3, qd = id & 7;
            size_t off = base + (size_t)(j0 + r) * HD_ + qd * 8;
            *reinterpret_cast<uint4*>(&QVh[r][qd*8]) = *reinterpret_cast<const uint4*>(g_qh + off);
            *reinterpret_cast<uint4*>(&QVl[r][qd*8]) = *reinterpret_cast<const uint4*>(g_ql + off);
        }
        if (tid < 64) qns[tid] = c1 * g_qn[bh * TT + j0 + tid];
        __syncthreads();

        float S[8][4];
#pragma unroll
        for (int nf = 0; nf < 8; nf++)
#pragma unroll
            for (int r = 0; r < 4; r++) S[nf][r] = 0.f;
#pragma unroll
        for (int kf = 0; kf < 4; kf++) {
            const int row = 16 * w;
            const int c0  = kf * 16 + 2 * t;
            unsigned ah0 = *reinterpret_cast<unsigned*>(&Ksh[row+g  ][c0  ]);
            unsigned ah1 = *reinterpret_cast<unsigned*>(&Ksh[row+g+8][c0  ]);
            unsigned ah2 = *reinterpret_cast<unsigned*>(&Ksh[row+g  ][c0+8]);
            unsigned ah3 = *reinterpret_cast<unsigned*>(&Ksh[row+g+8][c0+8]);
            unsigned al0 = *reinterpret_cast<unsigned*>(&Ksl[row+g  ][c0  ]);
            unsigned al1 = *reinterpret_cast<unsigned*>(&Ksl[row+g+8][c0  ]);
            unsigned al2 = *reinterpret_cast<unsigned*>(&Ksl[row+g  ][c0+8]);
            unsigned al3 = *reinterpret_cast<unsigned*>(&Ksl[row+g+8][c0+8]);
#pragma unroll
            for (int nf = 0; nf < 8; nf++) {
                unsigned bh0 = *reinterpret_cast<unsigned*>(&QVh[nf*8+g][c0  ]);
                unsigned bh1 = *reinterpret_cast<unsigned*>(&QVh[nf*8+g][c0+8]);
                unsigned bl0 = *reinterpret_cast<unsigned*>(&QVl[nf*8+g][c0  ]);
                unsigned bl1 = *reinterpret_cast<unsigned*>(&QVl[nf*8+g][c0+8]);
                mma_bf16(S[nf], ah0, ah1, ah2, ah3, bh0, bh1);
                mma_bf16(S[nf], ah0, ah1, ah2, ah3, bl0, bl1);
                mma_bf16(S[nf], al0, al1, al2, al3, bh0, bh1);
            }
        }

        unsigned Ph[4][4], Pl[4][4];
#pragma unroll
        for (int nf = 0; nf < 8; nf++) {
            float qn0 = qns[nf*8 + 2*t], qn1 = qns[nf*8 + 2*t + 1];
            float p00 = fexp2(fmaf(m2c1, S[nf][0], knc0 + qn0));
            float p01 = fexp2(fmaf(m2c1, S[nf][1], knc0 + qn1));
            float p10 = fexp2(fmaf(m2c1, S[nf][2], knc8 + qn0));
            float p11 = fexp2(fmaf(m2c1, S[nf][3], knc8 + qn1));
            bf16 h00,l00,h01,l01,h10,l10,h11,l11;
            bsplit(p00,h00,l00); bsplit(p01,h01,l01);
            bsplit(p10,h10,l10); bsplit(p11,h11,l11);
            int kf = nf >> 1;
            if ((nf & 1) == 0) {
                Ph[kf][0] = packb(h00,h01); Ph[kf][1] = packb(h10,h11);
                Pl[kf][0] = packb(l00,l01); Pl[kf][1] = packb(l10,l11);
            } else {
                Ph[kf][2] = packb(h00,h01); Ph[kf][3] = packb(h10,h11);
                Pl[kf][2] = packb(l00,l01); Pl[kf][3] = packb(l10,l11);
            }
        }
        __syncthreads();

#pragma unroll
        for (int p = 0; p < 4; p++) {
            int id = tid + p * 128;
            int r  = id >> 3, qd = id & 7;
            size_t off = base + (size_t)r * TT + j0 + qd * 8;
            *reinterpret_cast<uint4*>(&QVh[r][qd*8]) = *reinterpret_cast<const uint4*>(g_vth + off);
            *reinterpret_cast<uint4*>(&QVl[r][qd*8]) = *reinterpret_cast<const uint4*>(g_vtl + off);
        }
        __syncthreads();

#pragma unroll
        for (int kf = 0; kf < 4; kf++) {
            const int jc = kf * 8 + t;
#pragma unroll
            for (int nf = 0; nf < 8; nf++) {
                const unsigned* rowh = reinterpret_cast<const unsigned*>(&QVh[nf*8+g][0]);
                const unsigned* rowl = reinterpret_cast<const unsigned*>(&QVl[nf*8+g][0]);
                unsigned bh0 = rowh[jc];
                unsigned bh1 = rowh[jc + 4];
                unsigned bl0 = rowl[jc];
                unsigned bl1 = rowl[jc + 4];
                mma_bf16(O[nf], Ph[kf][0],Ph[kf][1],Ph[kf][2],Ph[kf][3], bh0, bh1);
                mma_bf16(O[nf], Ph[kf][0],Ph[kf][1],Ph[kf][2],Ph[kf][3], bl0, bl1);
                mma_bf16(O[nf], Pl[kf][0],Pl[kf][1],Pl[kf][2],Pl[kf][3], bh0, bh1);
            }
        }
    }

    const int b_ = bh >> 4;
    const int h  = bh & 15;
#pragma unroll
    for (int nf = 0; nf < 8; nf++) {
        int d  = nf * 8 + 2 * t;
        int iA = i0 + 16*w + g;
        int iB = iA + 8;
        size_t oA = ((size_t)b_ * TT + iA) * DIM_ + h * HD_ + d;
        size_t oB = ((size_t)b_ * TT + iB) * DIM_ + h * HD_ + d;
        *reinterpret_cast<float2*>(g_attn + oA) = make_float2(O[nf][0], O[nf][1]);
        *reinterpret_cast<float2*>(g_attn + oB) = make_float2(O[nf][2], O[nf][3]);
    }
}

// ---------------------------------------------------------------------------
// kernel_launch — inputs: x, Wqkv, bqkv, r_sigma, Wproj, bproj
// ---------------------------------------------------------------------------
extern "C" void kernel_launch(void* const* d_in, const int* in_sizes, int n_in,
                              void* d_out, int out_size)
{
    (void)in_sizes; (void)n_in; (void)out_size;
    const float* x     = (const float*)d_in[0];
    const float* Wqkv  = (const float*)d_in[1];
    const float* bqkv  = (const float*)d_in[2];
    const float* sig   = (const float*)d_in[3];
    const float* Wproj = (const float*)d_in[4];
    const float* bproj = (const float*)d_in[5];
    float* out = (float*)d_out;

    // 1) QKV GEMM (tensor core, on-the-fly split) -> q,k + transposed v
    mma_gemm<0><<<dim3(N1/64, M1/128), 256>>>(x, Wqkv, bqkv, nullptr, N1);

    // 2) Row norms
    norms_kernel<<<(NROWS * 32) / 256, 256>>>();

    // 3) Attention (tensor core)
    attn_mma_kernel<<<dim3(TT/64, BB*HH), 128>>>(sig);

    // 4) Projection GEMM (tensor core, on-the-fly split) -> d_out
    mma_gemm<1><<<dim3(CC/64, M1/128), 256>>>(nullptr, Wproj, bproj, out, CC);
}

// round 9
// speedup vs baseline: 3.0469x; 1.1429x over previous
#include <cuda_runtime.h>
#include <cuda_bf16.h>
#include <cstdint>
#include <cstddef>

#define BB   2
#define TT   2048
#define CC   1024
#define DIM_ 1024
#define HH   16
#define HD_  64
#define M1   (BB*TT)        // 4096
#define N1   (3*DIM_)       // 3072
#define KDIM 1024
#define NROWS (BB*HH*TT)    // 65536

typedef __nv_bfloat16  bf16;
typedef __nv_bfloat162 bf162;

// ---------------------------------------------------------------------------
// Scratch — EXACTLY 64.5 MiB (proven footprint). No other globals.
// ---------------------------------------------------------------------------
__device__ __align__(16) bf16 g_qh[(size_t)NROWS*HD_], g_ql[(size_t)NROWS*HD_];
__device__ __align__(16) bf16 g_kh[(size_t)NROWS*HD_], g_kl[(size_t)NROWS*HD_];
__device__ __align__(16) bf16 g_vth[(size_t)NROWS*HD_], g_vtl[(size_t)NROWS*HD_];
__device__ float g_attn[(size_t)M1*DIM_];
__device__ float g_qn[NROWS], g_kn[NROWS];

// ---------------------------------------------------------------------------
// Helpers
// ---------------------------------------------------------------------------
__device__ __forceinline__ void bsplit(float x, bf16 &h, bf16 &l) {
    h = __float2bfloat16_rn(x);
    l = __float2bfloat16_rn(x - __bfloat162float(h));
}
__device__ __forceinline__ unsigned packb(bf16 a, bf16 b) {
    bf162 t; t.x = a; t.y = b;
    return *reinterpret_cast<unsigned*>(&t);
}
__device__ __forceinline__ void mma_bf16(float* c,
    unsigned a0, unsigned a1, unsigned a2, unsigned a3,
    unsigned b0, unsigned b1)
{
    asm volatile(
        "mma.sync.aligned.m16n8k16.row.col.f32.bf16.bf16.f32 "
        "{%0,%1,%2,%3},{%4,%5,%6,%7},{%8,%9},{%0,%1,%2,%3};\n"
        : "+f"(c[0]), "+f"(c[1]), "+f"(c[2]), "+f"(c[3])
        : "r"(a0), "r"(a1), "r"(a2), "r"(a3), "r"(b0), "r"(b1));
}
__device__ __forceinline__ uint32_t s2u(const void* p) {
    return (uint32_t)__cvta_generic_to_shared(p);
}
__device__ __forceinline__ void ldsm_x4(unsigned &r0, unsigned &r1,
                                        unsigned &r2, unsigned &r3, uint32_t a)
{
    asm volatile("ldmatrix.sync.aligned.m8n8.x4.shared.b16 {%0,%1,%2,%3}, [%4];"
        : "=r"(r0), "=r"(r1), "=r"(r2), "=r"(r3) : "r"(a));
}
// Fast 2^t (FMA pipe only), max rel err ~8e-6
__device__ __forceinline__ float fexp2(float t) {
    t = fmaxf(t, -125.0f);
    float fi = floorf(t);
    float f  = t - fi;
    float p  = 1.5403530e-4f;
    p = fmaf(p, f, 1.3333558e-3f);
    p = fmaf(p, f, 9.6181291e-3f);
    p = fmaf(p, f, 5.5504109e-2f);
    p = fmaf(p, f, 2.4022651e-1f);
    p = fmaf(p, f, 6.9314718e-1f);
    p = fmaf(p, f, 1.0f);
    return p * __int_as_float(((int)fi + 127) << 23);
}

// ---------------------------------------------------------------------------
// Tensor-core GEMM, on-the-fly fp32 -> hi/lo bf16 split, 3-pass MMA,
// ldmatrix fragment loads + register-prefetch software pipeline.
// CTA 128m x 64n, 8 warps (4m x 2n), warp 32x32, k-chunk 32.
// MODE 0: QKV -> scatter hi/lo bf16 (q,k natural; v transposed [d][t])
// MODE 1: proj -> fp32 d_out
// ---------------------------------------------------------------------------
template <int MODE>
__global__ void __launch_bounds__(256, 2)
mma_gemm(const float* __restrict__ A_g, const float* __restrict__ Bm,
         const float* __restrict__ bias, float* __restrict__ Cout, int Ncols)
{
    __shared__ __align__(16) bf16 Ash[128][40], Asl[128][40];
    __shared__ __align__(16) bf16 Bsh[64][40],  Bsl[64][40];

    const float* A = (MODE == 0) ? A_g : g_attn;
    const int tid = threadIdx.x;
    const int m0  = blockIdx.y * 128;
    const int n0  = blockIdx.x * 64;
    const int w   = tid >> 5, lane = tid & 31;
    const int wm  = w >> 1,  wn  = w & 1;
    const int g   = lane >> 2, t = lane & 3;

    const int bn  = tid & 63;      // B-fill: n within tile
    const int bkh = tid >> 6;      // B-fill: k-octet 0..3

    // ldmatrix lane-addressing (constant per thread)
    const int aRow = wm * 32 + (lane & 15);
    const int aCol = (lane & 16) >> 1;                 // 0 or 8
    const int bRow = wn * 32 + ((lane & 16) >> 1) + (lane & 7);
    const int bCol = lane & 8;                         // 0 or 8
    const uint32_t aBaseH = s2u(&Ash[aRow][aCol]);
    const uint32_t aBaseL = s2u(&Asl[aRow][aCol]);
    const uint32_t bBaseH = s2u(&Bsh[bRow][bCol]);
    const uint32_t bBaseL = s2u(&Bsl[bRow][bCol]);

    float C[2][4][4];
#pragma unroll
    for (int mf = 0; mf < 2; mf++)
#pragma unroll
        for (int nf = 0; nf < 4; nf++)
#pragma unroll
            for (int r = 0; r < 4; r++) C[mf][nf][r] = 0.f;

    float4 a_pf[4];
    float  b_pf[8];

    auto load_tile = [&](int k0) {
#pragma unroll
        for (int p = 0; p < 4; p++) {
            int id = tid + p * 256;
            int r  = id >> 3, c4 = id & 7;
            a_pf[p] = *(const float4*)(A + (size_t)(m0 + r) * KDIM + k0 + c4 * 4);
        }
#pragma unroll
        for (int kk2 = 0; kk2 < 4; kk2++) {
            int k = bkh * 8 + kk2 * 2;
            b_pf[kk2*2  ] = Bm[(size_t)(k0 + k    ) * Ncols + n0 + bn];
            b_pf[kk2*2+1] = Bm[(size_t)(k0 + k + 1) * Ncols + n0 + bn];
        }
    };
    auto store_tile = [&]() {
#pragma unroll
        for (int p = 0; p < 4; p++) {
            int id = tid + p * 256;
            int r  = id >> 3, c4 = id & 7;
            bf16 h0,l0,h1,l1,h2,l2,h3,l3;
            bsplit(a_pf[p].x,h0,l0); bsplit(a_pf[p].y,h1,l1);
            bsplit(a_pf[p].z,h2,l2); bsplit(a_pf[p].w,h3,l3);
            *reinterpret_cast<uint2*>(&Ash[r][c4*4]) = make_uint2(packb(h0,h1), packb(h2,h3));
            *reinterpret_cast<uint2*>(&Asl[r][c4*4]) = make_uint2(packb(l0,l1), packb(l2,l3));
        }
#pragma unroll
        for (int kk2 = 0; kk2 < 4; kk2++) {
            int k = bkh * 8 + kk2 * 2;
            bf16 h0,l0,h1,l1;
            bsplit(b_pf[kk2*2  ],h0,l0); bsplit(b_pf[kk2*2+1],h1,l1);
            *reinterpret_cast<unsigned*>(&Bsh[bn][k]) = packb(h0,h1);
            *reinterpret_cast<unsigned*>(&Bsl[bn][k]) = packb(l0,l1);
        }
    };

    load_tile(0);
    store_tile();
    __syncthreads();

    for (int k0 = 0; k0 < KDIM; k0 += 32) {
        const bool has_next = (k0 + 32 < KDIM);
        if (has_next) load_tile(k0 + 32);   // global loads overlap the MMAs below

#pragma unroll
        for (int ks = 0; ks < 2; ks++) {
            const uint32_t ksOff = (uint32_t)(ks * 16 * 2);   // bytes
            unsigned ah[2][4], al[2][4];
#pragma unroll
            for (int mf = 0; mf < 2; mf++) {
                const uint32_t mOff = (uint32_t)(mf * 16 * 40 * 2);
                ldsm_x4(ah[mf][0], ah[mf][1], ah[mf][2], ah[mf][3], aBaseH + mOff + ksOff);
                ldsm_x4(al[mf][0], al[mf][1], al[mf][2], al[mf][3], aBaseL + mOff + ksOff);
            }
            unsigned bh[4][2], bl[4][2];
#pragma unroll
            for (int nfp = 0; nfp < 2; nfp++) {
                const uint32_t nOff = (uint32_t)(nfp * 16 * 40 * 2);
                ldsm_x4(bh[nfp*2][0], bh[nfp*2][1], bh[nfp*2+1][0], bh[nfp*2+1][1],
                        bBaseH + nOff + ksOff);
                ldsm_x4(bl[nfp*2][0], bl[nfp*2][1], bl[nfp*2+1][0], bl[nfp*2+1][1],
                        bBaseL + nOff + ksOff);
            }
#pragma unroll
            for (int nf = 0; nf < 4; nf++)
#pragma unroll
                for (int mf = 0; mf < 2; mf++) {
                    mma_bf16(C[mf][nf], ah[mf][0],ah[mf][1],ah[mf][2],ah[mf][3],
                             bh[nf][0], bh[nf][1]);
                    mma_bf16(C[mf][nf], ah[mf][0],ah[mf][1],ah[mf][2],ah[mf][3],
                             bl[nf][0], bl[nf][1]);
                    mma_bf16(C[mf][nf], al[mf][0],al[mf][1],al[mf][2],al[mf][3],
                             bh[nf][0], bh[nf][1]);
                }
        }

        if (has_next) {
            __syncthreads();        // everyone done reading current tile
            store_tile();
            __syncthreads();        // next tile visible
        }
    }

    // Epilogue
#pragma unroll
    for (int mf = 0; mf < 2; mf++) {
#pragma unroll
        for (int nf = 0; nf < 4; nf++) {
            int n  = n0 + wn * 32 + nf * 8 + 2 * t;
            float b0 = bias[n], b1 = bias[n + 1];
            int mA = m0 + wm * 32 + mf * 16 + g;
            int mB = mA + 8;
            float v00 = C[mf][nf][0] + b0, v01 = C[mf][nf][1] + b1;
            float v10 = C[mf][nf][2] + b0, v11 = C[mf][nf][3] + b1;
            if (MODE == 0) {
                int s = n >> 10, h = (n >> 6) & 15, d = n & 63;
                int bhA = (mA >> 11) * HH + h, tA = mA & 2047;
                int bhB = (mB >> 11) * HH + h, tB = mB & 2047;
                bf16 h00,l00,h01,l01,h10,l10,h11,l11;
                bsplit(v00,h00,l00); bsplit(v01,h01,l01);
                bsplit(v10,h10,l10); bsplit(v11,h11,l11);
                if (s == 2) {
                    size_t iA0 = ((size_t)bhA * HD_ + d    ) * TT + tA;
                    size_t iA1 = ((size_t)bhA * HD_ + d + 1) * TT + tA;
                    size_t iB0 = ((size_t)bhB * HD_ + d    ) * TT + tB;
                    size_t iB1 = ((size_t)bhB * HD_ + d + 1) * TT + tB;
                    g_vth[iA0] = h00; g_vtl[iA0] = l00;
                    g_vth[iA1] = h01; g_vtl[iA1] = l01;
                    g_vth[iB0] = h10; g_vtl[iB0] = l10;
                    g_vth[iB1] = h11; g_vtl[iB1] = l11;
                } else {
                    bf16* ph = (s == 0) ? g_qh : g_kh;
                    bf16* pl = (s == 0) ? g_ql : g_kl;
                    size_t iA = ((size_t)bhA * TT + tA) * HD_ + d;
                    size_t iB = ((size_t)bhB * TT + tB) * HD_ + d;
                    *reinterpret_cast<unsigned*>(ph + iA) = packb(h00, h01);
                    *reinterpret_cast<unsigned*>(pl + iA) = packb(l00, l01);
                    *reinterpret_cast<unsigned*>(ph + iB) = packb(h10, h11);
                    *reinterpret_cast<unsigned*>(pl + iB) = packb(l10, l11);
                }
            } else {
                *reinterpret_cast<float2*>(&Cout[(size_t)mA * Ncols + n]) = make_float2(v00, v01);
                *reinterpret_cast<float2*>(&Cout[(size_t)mB * Ncols + n]) = make_float2(v10, v11);
            }
        }
    }
}

// ---------------------------------------------------------------------------
// Row norms from hi/lo bf16 q,k — one warp per (b,h,t) row  (proven)
// ---------------------------------------------------------------------------
__global__ void norms_kernel()
{
    int w    = (blockIdx.x * blockDim.x + threadIdx.x) >> 5;
    int lane = threadIdx.x & 31;
    size_t o = (size_t)w * HD_ + lane * 2;
    bf162 qh = *reinterpret_cast<bf162*>(g_qh + o);
    bf162 ql = *reinterpret_cast<bf162*>(g_ql + o);
    bf162 kh = *reinterpret_cast<bf162*>(g_kh + o);
    bf162 kl = *reinterpret_cast<bf162*>(g_kl + o);
    float q0 = __bfloat162float(qh.x) + __bfloat162float(ql.x);
    float q1 = __bfloat162float(qh.y) + __bfloat162float(ql.y);
    float k0 = __bfloat162float(kh.x) + __bfloat162float(kl.x);
    float k1 = __bfloat162float(kh.y) + __bfloat162float(kl.y);
    float sq = q0*q0 + q1*q1;
    float sk = k0*k0 + k1*k1;
#pragma unroll
    for (int off = 16; off; off >>= 1) {
        sq += __shfl_xor_sync(0xFFFFFFFFu, sq, off);
        sk += __shfl_xor_sync(0xFFFFFFFFu, sk, off);
    }
    if (lane == 0) { g_qn[w] = sq; g_kn[w] = sk; }
}

// ---------------------------------------------------------------------------
// Attention (round-6/7 proven, unchanged)
// ---------------------------------------------------------------------------
__global__ void __launch_bounds__(128)
attn_mma_kernel(const float* __restrict__ sigp)
{
    __shared__ __align__(16) bf16 Ksh[64][72], Ksl[64][72];
    __shared__ __align__(16) bf16 QVh[64][72], QVl[64][72];
    __shared__ float qns[64];

    const int tid  = threadIdx.x;
    const int w    = tid >> 5, lane = tid & 31;
    const int g    = lane >> 2, t = lane & 3;
    const int bh   = blockIdx.y;
    const int i0   = blockIdx.x * 64;
    const size_t base = (size_t)bh * TT * HD_;

    const float sigma = *sigp;
    const float c1    = -sigma * 1.4426950408889634f;
    const float m2c1  = -2.0f * c1;

#pragma unroll
    for (int p = 0; p < 4; p++) {
        int id = tid + p * 128;
        int r  = id >> 3, qd = id & 7;
        size_t off = base + (size_t)(i0 + r) * HD_ + qd * 8;
        *reinterpret_cast<uint4*>(&Ksh[r][qd*8]) = *reinterpret_cast<const uint4*>(g_kh + off);
        *reinterpret_cast<uint4*>(&Ksl[r][qd*8]) = *reinterpret_cast<const uint4*>(g_kl + off);
    }
    const float knc0 = c1 * g_kn[bh * TT + i0 + 16*w + g];
    const float knc8 = c1 * g_kn[bh * TT + i0 + 16*w + 8 + g];

    float O[8][4];
#pragma unroll
    for (int nf = 0; nf < 8; nf++)
#pragma unroll
        for (int r = 0; r < 4; r++) O[nf][r] = 0.f;

    for (int j0 = 0; j0 < TT; j0 += 64) {
        __syncthreads();
#pragma unroll
        for (int p = 0; p < 4; p++) {
            int id = tid + p * 128;
            int r  = id >> 3, qd = id & 7;
            size_t off = base + (size_t)(j0 + r) * HD_ + qd * 8;
            *reinterpret_cast<uint4*>(&QVh[r][qd*8]) = *reinterpret_cast<const uint4*>(g_qh + off);
            *reinterpret_cast<uint4*>(&QVl[r][qd*8]) = *reinterpret_cast<const uint4*>(g_ql + off);
        }
        if (tid < 64) qns[tid] = c1 * g_qn[bh * TT + j0 + tid];
        __syncthreads();

        float S[8][4];
#pragma unroll
        for (int nf = 0; nf < 8; nf++)
#pragma unroll
            for (int r = 0; r < 4; r++) S[nf][r] = 0.f;
#pragma unroll
        for (int kf = 0; kf < 4; kf++) {
            const int row = 16 * w;
            const int c0  = kf * 16 + 2 * t;
            unsigned ah0 = *reinterpret_cast<unsigned*>(&Ksh[row+g  ][c0  ]);
            unsigned ah1 = *reinterpret_cast<unsigned*>(&Ksh[row+g+8][c0  ]);
            unsigned ah2 = *reinterpret_cast<unsigned*>(&Ksh[row+g  ][c0+8]);
            unsigned ah3 = *reinterpret_cast<unsigned*>(&Ksh[row+g+8][c0+8]);
            unsigned al0 = *reinterpret_cast<unsigned*>(&Ksl[row+g  ][c0  ]);
            unsigned al1 = *reinterpret_cast<unsigned*>(&Ksl[row+g+8][c0  ]);
            unsigned al2 = *reinterpret_cast<unsigned*>(&Ksl[row+g  ][c0+8]);
            unsigned al3 = *reinterpret_cast<unsigned*>(&Ksl[row+g+8][c0+8]);
#pragma unroll
            for (int nf = 0; nf < 8; nf++) {
                unsigned bh0 = *reinterpret_cast<unsigned*>(&QVh[nf*8+g][c0  ]);
                unsigned bh1 = *reinterpret_cast<unsigned*>(&QVh[nf*8+g][c0+8]);
                unsigned bl0 = *reinterpret_cast<unsigned*>(&QVl[nf*8+g][c0  ]);
                unsigned bl1 = *reinterpret_cast<unsigned*>(&QVl[nf*8+g][c0+8]);
                mma_bf16(S[nf], ah0, ah1, ah2, ah3, bh0, bh1);
                mma_bf16(S[nf], ah0, ah1, ah2, ah3, bl0, bl1);
                mma_bf16(S[nf], al0, al1, al2, al3, bh0, bh1);
            }
        }

        unsigned Ph[4][4], Pl[4][4];
#pragma unroll
        for (int nf = 0; nf < 8; nf++) {
            float qn0 = qns[nf*8 + 2*t], qn1 = qns[nf*8 + 2*t + 1];
            float p00 = fexp2(fmaf(m2c1, S[nf][0], knc0 + qn0));
            float p01 = fexp2(fmaf(m2c1, S[nf][1], knc0 + qn1));
            float p10 = fexp2(fmaf(m2c1, S[nf][2], knc8 + qn0));
            float p11 = fexp2(fmaf(m2c1, S[nf][3], knc8 + qn1));
            bf16 h00,l00,h01,l01,h10,l10,h11,l11;
            bsplit(p00,h00,l00); bsplit(p01,h01,l01);
            bsplit(p10,h10,l10); bsplit(p11,h11,l11);
            int kf = nf >> 1;
            if ((nf & 1) == 0) {
                Ph[kf][0] = packb(h00,h01); Ph[kf][1] = packb(h10,h11);
                Pl[kf][0] = packb(l00,l01); Pl[kf][1] = packb(l10,l11);
            } else {
                Ph[kf][2] = packb(h00,h01); Ph[kf][3] = packb(h10,h11);
                Pl[kf][2] = packb(l00,l01); Pl[kf][3] = packb(l10,l11);
            }
        }
        __syncthreads();

#pragma unroll
        for (int p = 0; p < 4; p++) {
            int id = tid + p * 128;
            int r  = id >> 3, qd = id & 7;
            size_t off = base + (size_t)r * TT + j0 + qd * 8;
            *reinterpret_cast<uint4*>(&QVh[r][qd*8]) = *reinterpret_cast<const uint4*>(g_vth + off);
            *reinterpret_cast<uint4*>(&QVl[r][qd*8]) = *reinterpret_cast<const uint4*>(g_vtl + off);
        }
        __syncthreads();

#pragma unroll
        for (int kf = 0; kf < 4; kf++) {
            const int jc = kf * 8 + t;
#pragma unroll
            for (int nf = 0; nf < 8; nf++) {
                const unsigned* rowh = reinterpret_cast<const unsigned*>(&QVh[nf*8+g][0]);
                const unsigned* rowl = reinterpret_cast<const unsigned*>(&QVl[nf*8+g][0]);
                unsigned bh0 = rowh[jc];
                unsigned bh1 = rowh[jc + 4];
                unsigned bl0 = rowl[jc];
                unsigned bl1 = rowl[jc + 4];
                mma_bf16(O[nf], Ph[kf][0],Ph[kf][1],Ph[kf][2],Ph[kf][3], bh0, bh1);
                mma_bf16(O[nf], Ph[kf][0],Ph[kf][1],Ph[kf][2],Ph[kf][3], bl0, bl1);
                mma_bf16(O[nf], Pl[kf][0],Pl[kf][1],Pl[kf][2],Pl[kf][3], bh0, bh1);
            }
        }
    }

    const int b_ = bh >> 4;
    const int h  = bh & 15;
#pragma unroll
    for (int nf = 0; nf < 8; nf++) {
        int d  = nf * 8 + 2 * t;
        int iA = i0 + 16*w + g;
        int iB = iA + 8;
        size_t oA = ((size_t)b_ * TT + iA) * DIM_ + h * HD_ + d;
        size_t oB = ((size_t)b_ * TT + iB) * DIM_ + h * HD_ + d;
        *reinterpret_cast<float2*>(g_attn + oA) = make_float2(O[nf][0], O[nf][1]);
        *reinterpret_cast<float2*>(g_attn + oB) = make_float2(O[nf][2], O[nf][3]);
    }
}

// ---------------------------------------------------------------------------
// kernel_launch — inputs: x, Wqkv, bqkv, r_sigma, Wproj, bproj
// ---------------------------------------------------------------------------
extern "C" void kernel_launch(void* const* d_in, const int* in_sizes, int n_in,
                              void* d_out, int out_size)
{
    (void)in_sizes; (void)n_in; (void)out_size;
    const float* x     = (const float*)d_in[0];
    const float* Wqkv  = (const float*)d_in[1];
    const float* bqkv  = (const float*)d_in[2];
    const float* sig   = (const float*)d_in[3];
    const float* Wproj = (const float*)d_in[4];
    const float* bproj = (const float*)d_in[5];
    float* out = (float*)d_out;

    mma_gemm<0><<<dim3(N1/64, M1/128), 256>>>(x, Wqkv, bqkv, nullptr, N1);
    norms_kernel<<<(NROWS * 32) / 256, 256>>>();
    attn_mma_kernel<<<dim3(TT/64, BB*HH), 128>>>(sig);
    mma_gemm<1><<<dim3(CC/64, M1/128), 256>>>(nullptr, Wproj, bproj, out, CC);
}